// round 16
// baseline (speedup 1.0000x reference)
#include <cuda_runtime.h>
#include <cuda_fp16.h>
#include <math.h>

// ---------------------------------------------------------------------------
// GIN (3 GINConv layers + BN + ReLU + MLP head)
//   N_NODES=100000, N_EDGES=1200000, D_IN=128, D_H=64, N_GRAPHS=256
// R15 changes vs R14 (264.2us):
//   * gemmA: A-tile split into two 64-wide k-phases -> 35.8KB static smem,
//     __launch_bounds__(256,6) -> ~6 blocks/SM, 0.88 waves (was 1.32).
//   * bsum launch deleted: scatter_scan block-reduces deg[0..bid*1024)
//     inline to get its offset. 12 launches total.
//   * all other kernels byte-identical to R14.
// ---------------------------------------------------------------------------

#define MAX_NODES 100000
#define MAX_EDGES 1200000
#define NGRAPH    256
#define SCAN_B    1024
#define BPAD 136                    // halves stride, Bs rows (k=128 +8)
#define MPAD 72                     // halves stride, 64-wide tiles (64+8)

__device__ uint2 g_zh  [MAX_NODES * 16 + 16];     // fp16 aggregated rows
__device__ uint2 g_hh  [MAX_NODES * 16 + 16];     // fp16 activation rows
__device__ float g_pool[NGRAPH * 192];
__device__ int   g_deg [MAX_NODES + 1];
__device__ int   g_row [MAX_NODES + 1];
__device__ int   g_cur [MAX_NODES];
__device__ int   g_col [MAX_EDGES];

__device__ __forceinline__ float4 h2f4(uint2 u) {
    __half2 a = *(__half2*)&u.x, b = *(__half2*)&u.y;
    float2 fa = __half22float2(a), fb = __half22float2(b);
    return make_float4(fa.x, fa.y, fb.x, fb.y);
}
__device__ __forceinline__ uint2 f4h(float a, float b, float c, float d) {
    __half2 lo = __floats2half2_rn(a, b), hi = __floats2half2_rn(c, d);
    uint2 u; u.x = *(unsigned*)&lo; u.y = *(unsigned*)&hi; return u;
}

__device__ __forceinline__ void mma16816(float* c,
    unsigned a0, unsigned a1, unsigned a2, unsigned a3,
    unsigned b0, unsigned b1)
{
    asm volatile(
        "mma.sync.aligned.m16n8k16.row.col.f32.f16.f16.f32 "
        "{%0,%1,%2,%3}, {%4,%5,%6,%7}, {%8,%9}, {%0,%1,%2,%3};"
        : "+f"(c[0]), "+f"(c[1]), "+f"(c[2]), "+f"(c[3])
        : "r"(a0), "r"(a1), "r"(a2), "r"(a3), "r"(b0), "r"(b1));
}

// ---------------------------------------------------------------------------
__global__ void zero_both_kernel(int* __restrict__ deg, int nd,
                                 float* __restrict__ pool, int np) {
    int i = blockIdx.x * blockDim.x + threadIdx.x;
    if (i < nd) deg[i] = 0;
    if (i < np) pool[i] = 0.f;
}

// ---------------------------------------------------------------------------
// CSR build
// ---------------------------------------------------------------------------
__global__ void hist_kernel(const int* __restrict__ ei, int* __restrict__ deg, int n_edges) {
    int e = blockIdx.x * blockDim.x + threadIdx.x;
    if (e < n_edges) atomicAdd(deg + __ldg(ei + n_edges + e), 1);
}

// Hillis-Steele block scan; block offset computed INLINE by block-reducing
// deg[0 .. bid*SCAN_B) (no separate bsum kernel).
__global__ void scatter_scan_kernel(const int* __restrict__ deg,
                                    int* __restrict__ rowptr, int* __restrict__ cur, int n) {
    __shared__ int sm[SCAN_B];
    __shared__ int boff;
    int bid = blockIdx.x;
    int tid = threadIdx.x;

    // ---- block offset: sum of deg before this block ----
    int lim = bid * SCAN_B; if (lim > n) lim = n;
    int tot = 0;
    for (int i = tid; i < lim; i += SCAN_B) tot += __ldg(deg + i);
    sm[tid] = tot;
    __syncthreads();
#pragma unroll
    for (int off = SCAN_B / 2; off > 0; off >>= 1) {
        if (tid < off) sm[tid] += sm[tid + off];
        __syncthreads();
    }
    if (tid == 0) boff = sm[0];
    __syncthreads();

    // ---- intra-block scan ----
    int i = bid * SCAN_B + tid;
    int v = (i < n) ? deg[i] : 0;
    sm[tid] = v;
    __syncthreads();
#pragma unroll
    for (int off = 1; off < SCAN_B; off *= 2) {
        int t = (tid >= off) ? sm[tid - off] : 0;
        __syncthreads();
        sm[tid] += t;
        __syncthreads();
    }
    int excl = sm[tid] - v + boff;
    if (i < n) { rowptr[i] = excl; cur[i] = excl; }
    if (i == n - 1) rowptr[n] = excl + v;
}

__global__ void fill_kernel(const int* __restrict__ ei, int* __restrict__ cur,
                            int* __restrict__ col, int n_edges) {
    int e = blockIdx.x * blockDim.x + threadIdx.x;
    if (e >= n_edges) return;
    int s = __ldg(ei + e);
    int d = __ldg(ei + n_edges + e);
    int pos = atomicAdd(cur + d, 1);
    col[pos] = s;
}

// ---------------------------------------------------------------------------
// Pull aggregation over fp16 rows; fp32 accumulate; fp16 output. 16 thr/node.
// ---------------------------------------------------------------------------
__global__ void pull64h_kernel(const uint2* __restrict__ hh,
                               const int* __restrict__ rowptr,
                               const int* __restrict__ col,
                               uint2* __restrict__ zh, int n_nodes) {
    int t = blockIdx.x * blockDim.x + threadIdx.x;
    int node = t >> 4, lane = t & 15;
    if (node >= n_nodes) return;
    float4 acc = h2f4(__ldg(hh + (size_t)node * 16 + lane));
    int e   = __ldg(rowptr + node);
    int end = __ldg(rowptr + node + 1);
    for (; e + 8 <= end; e += 8) {
        int s0 = __ldg(col + e),     s1 = __ldg(col + e + 1);
        int s2 = __ldg(col + e + 2), s3 = __ldg(col + e + 3);
        int s4 = __ldg(col + e + 4), s5 = __ldg(col + e + 5);
        int s6 = __ldg(col + e + 6), s7 = __ldg(col + e + 7);
        float4 v0 = h2f4(__ldg(hh + (size_t)s0 * 16 + lane));
        float4 v1 = h2f4(__ldg(hh + (size_t)s1 * 16 + lane));
        float4 v2 = h2f4(__ldg(hh + (size_t)s2 * 16 + lane));
        float4 v3 = h2f4(__ldg(hh + (size_t)s3 * 16 + lane));
        float4 v4 = h2f4(__ldg(hh + (size_t)s4 * 16 + lane));
        float4 v5 = h2f4(__ldg(hh + (size_t)s5 * 16 + lane));
        float4 v6 = h2f4(__ldg(hh + (size_t)s6 * 16 + lane));
        float4 v7 = h2f4(__ldg(hh + (size_t)s7 * 16 + lane));
        acc.x += ((v0.x + v1.x) + (v2.x + v3.x)) + ((v4.x + v5.x) + (v6.x + v7.x));
        acc.y += ((v0.y + v1.y) + (v2.y + v3.y)) + ((v4.y + v5.y) + (v6.y + v7.y));
        acc.z += ((v0.z + v1.z) + (v2.z + v3.z)) + ((v4.z + v5.z) + (v6.z + v7.z));
        acc.w += ((v0.w + v1.w) + (v2.w + v3.w)) + ((v4.w + v5.w) + (v6.w + v7.w));
    }
    for (; e + 4 <= end; e += 4) {
        int s0 = __ldg(col + e),     s1 = __ldg(col + e + 1);
        int s2 = __ldg(col + e + 2), s3 = __ldg(col + e + 3);
        float4 v0 = h2f4(__ldg(hh + (size_t)s0 * 16 + lane));
        float4 v1 = h2f4(__ldg(hh + (size_t)s1 * 16 + lane));
        float4 v2 = h2f4(__ldg(hh + (size_t)s2 * 16 + lane));
        float4 v3 = h2f4(__ldg(hh + (size_t)s3 * 16 + lane));
        acc.x += (v0.x + v1.x) + (v2.x + v3.x);
        acc.y += (v0.y + v1.y) + (v2.y + v3.y);
        acc.z += (v0.z + v1.z) + (v2.z + v3.z);
        acc.w += (v0.w + v1.w) + (v2.w + v3.w);
    }
    for (; e < end; e++) {
        int s = __ldg(col + e);
        float4 v = h2f4(__ldg(hh + (size_t)s * 16 + lane));
        acc.x += v.x; acc.y += v.y; acc.z += v.z; acc.w += v.w;
    }
    zh[(size_t)node * 16 + lane] = f4h(acc.x, acc.y, acc.z, acc.w);
}

// ---------------------------------------------------------------------------
// gemmA_hmma: hh = fp16(x @ w1) on tensor cores, TWO 64-wide k-phases.
// As[128][MPAD] (18.4KB) reloaded per phase; Bs[64][BPAD] full k (17.4KB).
// Static smem ~35.8KB, 6 blocks/SM target.
// ---------------------------------------------------------------------------
__global__ __launch_bounds__(256, 6) void gemmA_hmma_kernel(
    const float* __restrict__ x, const float* __restrict__ w1,
    uint2* __restrict__ hh, int n_nodes)
{
    __shared__ __half As[128 * MPAD];
    __shared__ __half Bs[64 * BPAD];
    int tid = threadIdx.x;
    int nbase = blockIdx.x * 128;

    for (int i = tid; i < 128 * 64; i += 256) {
        int k = i >> 6, n = i & 63;
        Bs[n * BPAD + k] = __float2half(__ldg(w1 + i));
    }

    int wid = tid >> 5, lane = tid & 31;
    int r0 = wid * 16 + (lane >> 2);
    int kp = (lane & 3) * 2;

    float c[8][4];
#pragma unroll
    for (int nt = 0; nt < 8; nt++)
#pragma unroll
        for (int j = 0; j < 4; j++) c[nt][j] = 0.f;

#pragma unroll
    for (int p = 0; p < 2; p++) {
        if (p) __syncthreads();      // prior phase's As reads complete
        for (int i4 = tid; i4 < 2048; i4 += 256) {   // 128 rows x 16 float4
            int row = i4 >> 4, k4 = i4 & 15;
            int gn = nbase + row; if (gn >= n_nodes) gn = n_nodes - 1;
            float4 v = __ldg((const float4*)(x + (size_t)gn * 128) + p * 16 + k4);
            __half2 h0 = __floats2half2_rn(v.x, v.y);
            __half2 h1 = __floats2half2_rn(v.z, v.w);
            unsigned* dst = (unsigned*)&As[row * MPAD + k4 * 4];
            dst[0] = *(unsigned*)&h0;
            dst[1] = *(unsigned*)&h1;
        }
        __syncthreads();             // also covers the Bs load on p==0

#pragma unroll
        for (int kt = 0; kt < 4; kt++) {
            int ks = kt * 16 + kp;           // As k index (0..63)
            int kg = p * 64 + ks;            // Bs k index (0..127)
            unsigned a0 = *(unsigned*)&As[r0 * MPAD + ks];
            unsigned a1 = *(unsigned*)&As[(r0 + 8) * MPAD + ks];
            unsigned a2 = *(unsigned*)&As[r0 * MPAD + ks + 8];
            unsigned a3 = *(unsigned*)&As[(r0 + 8) * MPAD + ks + 8];
#pragma unroll
            for (int nt = 0; nt < 8; nt++) {
                int n = nt * 8 + (lane >> 2);
                unsigned b0 = *(unsigned*)&Bs[n * BPAD + kg];
                unsigned b1 = *(unsigned*)&Bs[n * BPAD + kg + 8];
                mma16816(c[nt], a0, a1, a2, a3, b0, b1);
            }
        }
    }

    int colp = (lane & 3) * 2;
#pragma unroll
    for (int rr = 0; rr < 2; rr++) {
        int node = nbase + r0 + rr * 8;
        if (node >= n_nodes) continue;
        __half* hrow = (__half*)(hh + (size_t)node * 16);
#pragma unroll
        for (int nt = 0; nt < 8; nt++) {
            __half2 hv = __floats2half2_rn(c[nt][rr * 2 + 0], c[nt][rr * 2 + 1]);
            *(unsigned*)&hrow[nt * 8 + colp] = *(unsigned*)&hv;
        }
    }
}

// ---------------------------------------------------------------------------
// mlpB_hmma (layer-1 tail): h = relu( relu(BN(zh+b1)) @ w2 + b2 ). (R14)
// ---------------------------------------------------------------------------
__global__ __launch_bounds__(256) void mlpB_hmma_kernel(
    const uint2* __restrict__ zh,
    const float* __restrict__ b1,
    const float* __restrict__ gg, const float* __restrict__ bt,
    const float* __restrict__ rm, const float* __restrict__ rv,
    const float* __restrict__ w2, const float* __restrict__ b2,
    uint2*       __restrict__ hh,
    const int*   __restrict__ batch,
    float*       __restrict__ pool, int pool_off, int n_nodes)
{
    __shared__ __half As[128 * MPAD];
    __shared__ __half Bs[64 * MPAD];
    __shared__ float2 scsh[64];
    int tid = threadIdx.x;
    int nbase = blockIdx.x * 128;

    if (tid < 64) {
        float sc = __ldg(gg + tid) * rsqrtf(__ldg(rv + tid) + 1e-5f);
        float sh = (__ldg(b1 + tid) - __ldg(rm + tid)) * sc + __ldg(bt + tid);
        scsh[tid] = make_float2(sc, sh);
    }
    for (int i = tid; i < 64 * 64; i += 256) {
        int k = i >> 6, n = i & 63;
        Bs[n * MPAD + k] = __float2half(__ldg(w2 + i));
    }
    __syncthreads();

    for (int i4 = tid; i4 < 2048; i4 += 256) {
        int row = i4 >> 4, k4 = i4 & 15;
        int gn = nbase + row; if (gn >= n_nodes) gn = n_nodes - 1;
        float4 v = h2f4(__ldg(zh + (size_t)gn * 16 + k4));
        int k = k4 * 4;
        float2 s0 = scsh[k], s1 = scsh[k + 1], s2 = scsh[k + 2], s3 = scsh[k + 3];
        float h0 = fmaxf(fmaf(v.x, s0.x, s0.y), 0.f);
        float h1 = fmaxf(fmaf(v.y, s1.x, s1.y), 0.f);
        float h2v = fmaxf(fmaf(v.z, s2.x, s2.y), 0.f);
        float h3 = fmaxf(fmaf(v.w, s3.x, s3.y), 0.f);
        __half2 p0 = __floats2half2_rn(h0, h1), p1 = __floats2half2_rn(h2v, h3);
        unsigned* dst = (unsigned*)&As[row * MPAD + k];
        dst[0] = *(unsigned*)&p0;
        dst[1] = *(unsigned*)&p1;
    }
    __syncthreads();

    int wid = tid >> 5, lane = tid & 31;
    int r0 = wid * 16 + (lane >> 2);
    int kp = (lane & 3) * 2;

    float c[8][4];
#pragma unroll
    for (int nt = 0; nt < 8; nt++)
#pragma unroll
        for (int j = 0; j < 4; j++) c[nt][j] = 0.f;

#pragma unroll
    for (int kt = 0; kt < 4; kt++) {
        int kb = kt * 16 + kp;
        unsigned a0 = *(unsigned*)&As[r0 * MPAD + kb];
        unsigned a1 = *(unsigned*)&As[(r0 + 8) * MPAD + kb];
        unsigned a2 = *(unsigned*)&As[r0 * MPAD + kb + 8];
        unsigned a3 = *(unsigned*)&As[(r0 + 8) * MPAD + kb + 8];
#pragma unroll
        for (int nt = 0; nt < 8; nt++) {
            int n = nt * 8 + (lane >> 2);
            unsigned b0 = *(unsigned*)&Bs[n * MPAD + kb];
            unsigned b1 = *(unsigned*)&Bs[n * MPAD + kb + 8];
            mma16816(c[nt], a0, a1, a2, a3, b0, b1);
        }
    }

    int colp = (lane & 3) * 2;
#pragma unroll
    for (int rr = 0; rr < 2; rr++) {
        int node = nbase + r0 + rr * 8;
        if (node >= n_nodes) continue;
        __half* hrow = (__half*)(hh + (size_t)node * 16);
        float*  prow = pool + (size_t)__ldg(batch + node) * 192 + pool_off;
#pragma unroll
        for (int nt = 0; nt < 8; nt++) {
            int cA = nt * 8 + colp;
            float v0 = fmaxf(c[nt][rr * 2 + 0] + __ldg(b2 + cA), 0.f);
            float v1 = fmaxf(c[nt][rr * 2 + 1] + __ldg(b2 + cA + 1), 0.f);
            __half2 hv = __floats2half2_rn(v0, v1);
            *(unsigned*)&hrow[cA] = *(unsigned*)&hv;
            asm volatile("red.global.add.v2.f32 [%0], {%1,%2};"
                         :: "l"(prow + cA), "f"(v0), "f"(v1) : "memory");
        }
    }
}

// ---------------------------------------------------------------------------
// mlp64_hmma (layers 2/3). (R14)
// ---------------------------------------------------------------------------
__global__ __launch_bounds__(256) void mlp64_hmma_kernel(
    const uint2* __restrict__ zh,
    const float* __restrict__ w1, const float* __restrict__ b1,
    const float* __restrict__ gg, const float* __restrict__ bt,
    const float* __restrict__ rm, const float* __restrict__ rv,
    const float* __restrict__ w2, const float* __restrict__ b2,
    uint2*       __restrict__ hh,
    const int*   __restrict__ batch,
    float*       __restrict__ pool, int pool_off, int n_nodes)
{
    __shared__ __half As[128 * MPAD];
    __shared__ __half Bs[64 * MPAD];
    __shared__ float2 scsh[64];
    int tid = threadIdx.x;
    int nbase = blockIdx.x * 128;

    if (tid < 64) {
        float sc = __ldg(gg + tid) * rsqrtf(__ldg(rv + tid) + 1e-5f);
        float sh = (__ldg(b1 + tid) - __ldg(rm + tid)) * sc + __ldg(bt + tid);
        scsh[tid] = make_float2(sc, sh);
    }
    for (int i = tid; i < 64 * 64; i += 256) {
        int k = i >> 6, n = i & 63;
        Bs[n * MPAD + k] = __float2half(__ldg(w1 + i));
    }
    for (int i = tid; i < 1024; i += 256) {
        int row = i >> 3, q4 = i & 7;
        int gn = nbase + row; if (gn >= n_nodes) gn = n_nodes - 1;
        uint4 v = __ldg((const uint4*)(zh + (size_t)gn * 16) + q4);
        *(uint4*)&As[row * MPAD + q4 * 8] = v;
    }
    __syncthreads();

    int wid = tid >> 5, lane = tid & 31;
    int r0 = wid * 16 + (lane >> 2);
    int kp = (lane & 3) * 2;
    int colp = (lane & 3) * 2;

    float c[8][4];
#pragma unroll
    for (int nt = 0; nt < 8; nt++)
#pragma unroll
        for (int j = 0; j < 4; j++) c[nt][j] = 0.f;

#pragma unroll
    for (int kt = 0; kt < 4; kt++) {
        int kb = kt * 16 + kp;
        unsigned a0 = *(unsigned*)&As[r0 * MPAD + kb];
        unsigned a1 = *(unsigned*)&As[(r0 + 8) * MPAD + kb];
        unsigned a2 = *(unsigned*)&As[r0 * MPAD + kb + 8];
        unsigned a3 = *(unsigned*)&As[(r0 + 8) * MPAD + kb + 8];
#pragma unroll
        for (int nt = 0; nt < 8; nt++) {
            int n = nt * 8 + (lane >> 2);
            unsigned b0 = *(unsigned*)&Bs[n * MPAD + kb];
            unsigned b1 = *(unsigned*)&Bs[n * MPAD + kb + 8];
            mma16816(c[nt], a0, a1, a2, a3, b0, b1);
        }
    }

#pragma unroll
    for (int nt = 0; nt < 8; nt++) {
        int cA = nt * 8 + colp, cB = cA + 1;
        float2 sA = scsh[cA], sB = scsh[cB];
        float h00 = fmaxf(fmaf(c[nt][0], sA.x, sA.y), 0.f);
        float h01 = fmaxf(fmaf(c[nt][1], sB.x, sB.y), 0.f);
        float h10 = fmaxf(fmaf(c[nt][2], sA.x, sA.y), 0.f);
        float h11 = fmaxf(fmaf(c[nt][3], sB.x, sB.y), 0.f);
        __half2 p0 = __floats2half2_rn(h00, h01);
        __half2 p1 = __floats2half2_rn(h10, h11);
        *(unsigned*)&As[r0 * MPAD + cA]       = *(unsigned*)&p0;
        *(unsigned*)&As[(r0 + 8) * MPAD + cA] = *(unsigned*)&p1;
    }
    __syncthreads();

    for (int i = tid; i < 64 * 64; i += 256) {
        int k = i >> 6, n = i & 63;
        Bs[n * MPAD + k] = __float2half(__ldg(w2 + i));
    }
    __syncthreads();

#pragma unroll
    for (int nt = 0; nt < 8; nt++)
#pragma unroll
        for (int j = 0; j < 4; j++) c[nt][j] = 0.f;

#pragma unroll
    for (int kt = 0; kt < 4; kt++) {
        int kb = kt * 16 + kp;
        unsigned a0 = *(unsigned*)&As[r0 * MPAD + kb];
        unsigned a1 = *(unsigned*)&As[(r0 + 8) * MPAD + kb];
        unsigned a2 = *(unsigned*)&As[r0 * MPAD + kb + 8];
        unsigned a3 = *(unsigned*)&As[(r0 + 8) * MPAD + kb + 8];
#pragma unroll
        for (int nt = 0; nt < 8; nt++) {
            int n = nt * 8 + (lane >> 2);
            unsigned b0 = *(unsigned*)&Bs[n * MPAD + kb];
            unsigned b1 = *(unsigned*)&Bs[n * MPAD + kb + 8];
            mma16816(c[nt], a0, a1, a2, a3, b0, b1);
        }
    }

#pragma unroll
    for (int rr = 0; rr < 2; rr++) {
        int node = nbase + r0 + rr * 8;
        if (node >= n_nodes) continue;
        __half* hrow = (__half*)(hh + (size_t)node * 16);
        float*  prow = pool + (size_t)__ldg(batch + node) * 192 + pool_off;
#pragma unroll
        for (int nt = 0; nt < 8; nt++) {
            int cA = nt * 8 + colp;
            float v0 = fmaxf(c[nt][rr * 2 + 0] + __ldg(b2 + cA), 0.f);
            float v1 = fmaxf(c[nt][rr * 2 + 1] + __ldg(b2 + cA + 1), 0.f);
            __half2 hv = __floats2half2_rn(v0, v1);
            *(unsigned*)&hrow[cA] = *(unsigned*)&hv;
            asm volatile("red.global.add.v2.f32 [%0], {%1,%2};"
                         :: "l"(prow + cA), "f"(v0), "f"(v1) : "memory");
        }
    }
}

// ---------------------------------------------------------------------------
__global__ void final_kernel(const float* __restrict__ pool,
                             const float* __restrict__ lw1, const float* __restrict__ lb1,
                             const float* __restrict__ lw2, const float* __restrict__ lb2,
                             float* __restrict__ out)
{
    __shared__ float prow[192];
    __shared__ float hid[64];
    __shared__ float zz[2];
    int g = blockIdx.x, j = threadIdx.x;
    for (int k = j; k < 192; k += 64) prow[k] = pool[g * 192 + k];
    __syncthreads();
    float a = __ldg(lb1 + j);
    for (int k = 0; k < 192; k++) a = fmaf(prow[k], __ldg(lw1 + k * 64 + j), a);
    hid[j] = fmaxf(a, 0.f);
    __syncthreads();
    if (j < 2) {
        float zv = __ldg(lb2 + j);
#pragma unroll 8
        for (int k = 0; k < 64; k++) zv = fmaf(hid[k], __ldg(lw2 + k * 2 + j), zv);
        zz[j] = zv;
    }
    __syncthreads();
    if (j == 0) {
        float m   = fmaxf(zz[0], zz[1]);
        float lse = m + logf(expf(zz[0] - m) + expf(zz[1] - m));
        out[g * 2 + 0] = zz[0] - lse;
        out[g * 2 + 1] = zz[1] - lse;
    }
}

// ---------------------------------------------------------------------------
extern "C" void kernel_launch(void* const* d_in, const int* in_sizes, int n_in,
                              void* d_out, int out_size)
{
    const float* x     = (const float*)d_in[0];
    const int*   ei    = (const int*)  d_in[1];
    const int*   batch = (const int*)  d_in[2];

    int wi = (in_sizes[3] < 64) ? 4 : 3;
    const float* W[28];
    for (int i = 0; i < 28 && wi + i < n_in; i++) W[i] = (const float*)d_in[wi + i];

    int n_nodes = in_sizes[0] / 128;
    int n_edges = in_sizes[1] / 2;

    float *pool;
    uint2 *hh, *zh;
    int *deg, *row, *cur, *col;
    cudaGetSymbolAddress((void**)&zh,   g_zh);
    cudaGetSymbolAddress((void**)&hh,   g_hh);
    cudaGetSymbolAddress((void**)&pool, g_pool);
    cudaGetSymbolAddress((void**)&deg,  g_deg);
    cudaGetSymbolAddress((void**)&row,  g_row);
    cudaGetSymbolAddress((void**)&cur,  g_cur);
    cudaGetSymbolAddress((void**)&col,  g_col);

    float* out = (float*)d_out;

    int mlpBlocks  = (n_nodes + 127) / 128;
    int pullBlocks = (n_nodes * 16 + 255) / 256;
    int scanBlocks = (n_nodes + SCAN_B - 1) / SCAN_B;
    int zeroN      = n_nodes + 1;

    // ---- CSR build; gemmA_hmma is OUR launch #3/#4 region (profiled) ----
    zero_both_kernel<<<(zeroN + 255) / 256, 256>>>(deg, zeroN, pool, NGRAPH * 192); // 1
    hist_kernel<<<(n_edges + 255) / 256, 256>>>(ei, deg, n_edges);                  // 2
    gemmA_hmma_kernel<<<mlpBlocks, 256>>>(x, W[0], hh, n_nodes);                    // 3
    scatter_scan_kernel<<<scanBlocks, SCAN_B>>>(deg, row, cur, n_nodes);            // 4
    fill_kernel<<<(n_edges + 255) / 256, 256>>>(ei, cur, col, n_edges);             // 5

    // ---- layer 1 ----
    pull64h_kernel<<<pullBlocks, 256>>>(hh, row, col, zh, n_nodes);                 // 6
    mlpB_hmma_kernel<<<mlpBlocks, 256>>>(zh, W[1], W[2], W[3], W[4], W[5], W[6], W[7],
                                         hh, batch, pool, 0, n_nodes);              // 7

    // ---- layer 2 ----
    pull64h_kernel<<<pullBlocks, 256>>>(hh, row, col, zh, n_nodes);                 // 8
    mlp64_hmma_kernel<<<mlpBlocks, 256>>>(zh, W[8], W[9], W[10], W[11], W[12], W[13], W[14], W[15],
                                          hh, batch, pool, 64, n_nodes);            // 9

    // ---- layer 3 ----
    pull64h_kernel<<<pullBlocks, 256>>>(hh, row, col, zh, n_nodes);                 // 10
    mlp64_hmma_kernel<<<mlpBlocks, 256>>>(zh, W[16], W[17], W[18], W[19], W[20], W[21], W[22], W[23],
                                          hh, batch, pool, 128, n_nodes);           // 11

    final_kernel<<<NGRAPH, 64>>>(pool, W[24], W[25], W[26], W[27], out);            // 12
}

// round 17
// speedup vs baseline: 1.0965x; 1.0965x over previous
#include <cuda_runtime.h>
#include <cuda_fp16.h>
#include <math.h>

// ---------------------------------------------------------------------------
// GIN (3 GINConv layers + BN + ReLU + MLP head)
//   N_NODES=100000, N_EDGES=1200000, D_IN=128, D_H=64, N_GRAPHS=256
// R16 = R14 (264.2us) restored (R15's gemmA split + inline-scan both
// regressed and are reverted), plus ONE isolated tweak:
//   * pull64h: 8 threads/node x uint4 (was 16 x uint2) -> half the load
//     instrs + col reads, double per-thread ILP, same traffic/precision.
// ---------------------------------------------------------------------------

#define MAX_NODES 100000
#define MAX_EDGES 1200000
#define NGRAPH    256
#define SCAN_B    1024
#define MAX_SCAN_BLOCKS 128
#define APAD 136                    // halves stride, gemmA A tile (128+8)
#define BPAD 136
#define MPAD 72                     // halves stride, mlp tiles (64+8)

__device__ uint2 g_zh  [MAX_NODES * 16 + 16];     // fp16 aggregated rows
__device__ uint2 g_hh  [MAX_NODES * 16 + 16];     // fp16 activation rows
__device__ float g_pool[NGRAPH * 192];
__device__ int   g_deg [MAX_NODES + 1];
__device__ int   g_row [MAX_NODES + 1];
__device__ int   g_cur [MAX_NODES];
__device__ int   g_col [MAX_EDGES];
__device__ int   g_bsum[MAX_SCAN_BLOCKS];

__device__ __forceinline__ float4 h2f4(uint2 u) {
    __half2 a = *(__half2*)&u.x, b = *(__half2*)&u.y;
    float2 fa = __half22float2(a), fb = __half22float2(b);
    return make_float4(fa.x, fa.y, fb.x, fb.y);
}
__device__ __forceinline__ uint2 f4h(float a, float b, float c, float d) {
    __half2 lo = __floats2half2_rn(a, b), hi = __floats2half2_rn(c, d);
    uint2 u; u.x = *(unsigned*)&lo; u.y = *(unsigned*)&hi; return u;
}

__device__ __forceinline__ void mma16816(float* c,
    unsigned a0, unsigned a1, unsigned a2, unsigned a3,
    unsigned b0, unsigned b1)
{
    asm volatile(
        "mma.sync.aligned.m16n8k16.row.col.f32.f16.f16.f32 "
        "{%0,%1,%2,%3}, {%4,%5,%6,%7}, {%8,%9}, {%0,%1,%2,%3};"
        : "+f"(c[0]), "+f"(c[1]), "+f"(c[2]), "+f"(c[3])
        : "r"(a0), "r"(a1), "r"(a2), "r"(a3), "r"(b0), "r"(b1));
}

// accumulate 8 halves (uint4) into 8 fp32 accumulators
__device__ __forceinline__ void acc8(float* a, uint4 u) {
    float4 lo = h2f4(make_uint2(u.x, u.y));
    float4 hi = h2f4(make_uint2(u.z, u.w));
    a[0] += lo.x; a[1] += lo.y; a[2] += lo.z; a[3] += lo.w;
    a[4] += hi.x; a[5] += hi.y; a[6] += hi.z; a[7] += hi.w;
}

// ---------------------------------------------------------------------------
__global__ void zero_both_kernel(int* __restrict__ deg, int nd,
                                 float* __restrict__ pool, int np) {
    int i = blockIdx.x * blockDim.x + threadIdx.x;
    if (i < nd) deg[i] = 0;
    if (i < np) pool[i] = 0.f;
}

// ---------------------------------------------------------------------------
// CSR build (R14-exact: separate bsum + scatter_scan)
// ---------------------------------------------------------------------------
__global__ void hist_kernel(const int* __restrict__ ei, int* __restrict__ deg, int n_edges) {
    int e = blockIdx.x * blockDim.x + threadIdx.x;
    if (e < n_edges) atomicAdd(deg + __ldg(ei + n_edges + e), 1);
}

__global__ void bsum_kernel(const int* __restrict__ deg, int* __restrict__ bsum, int n) {
    __shared__ int sm[SCAN_B];
    int i = blockIdx.x * SCAN_B + threadIdx.x;
    sm[threadIdx.x] = (i < n) ? deg[i] : 0;
    __syncthreads();
#pragma unroll
    for (int off = SCAN_B / 2; off > 0; off >>= 1) {
        if (threadIdx.x < off) sm[threadIdx.x] += sm[threadIdx.x + off];
        __syncthreads();
    }
    if (threadIdx.x == 0) bsum[blockIdx.x] = sm[0];
}

__global__ void scatter_scan_kernel(const int* __restrict__ deg,
                                    const int* __restrict__ bsum,
                                    int* __restrict__ rowptr, int* __restrict__ cur, int n) {
    __shared__ int sm[SCAN_B];
    __shared__ int boff;
    int bid = blockIdx.x;
    if (threadIdx.x < 32) {
        int s = 0;
        for (int i = threadIdx.x; i < bid; i += 32) s += __ldg(bsum + i);
#pragma unroll
        for (int o = 16; o > 0; o >>= 1) s += __shfl_down_sync(0xffffffffu, s, o);
        if (threadIdx.x == 0) boff = s;
    }
    int i = bid * SCAN_B + threadIdx.x;
    int v = (i < n) ? deg[i] : 0;
    sm[threadIdx.x] = v;
    __syncthreads();
#pragma unroll
    for (int off = 1; off < SCAN_B; off *= 2) {
        int t = (threadIdx.x >= off) ? sm[threadIdx.x - off] : 0;
        __syncthreads();
        sm[threadIdx.x] += t;
        __syncthreads();
    }
    int excl = sm[threadIdx.x] - v + boff;
    if (i < n) { rowptr[i] = excl; cur[i] = excl; }
    if (i == n - 1) rowptr[n] = excl + v;
}

__global__ void fill_kernel(const int* __restrict__ ei, int* __restrict__ cur,
                            int* __restrict__ col, int n_edges) {
    int e = blockIdx.x * blockDim.x + threadIdx.x;
    if (e >= n_edges) return;
    int s = __ldg(ei + e);
    int d = __ldg(ei + n_edges + e);
    int pos = atomicAdd(cur + d, 1);
    col[pos] = s;
}

// ---------------------------------------------------------------------------
// Pull aggregation over fp16 rows; fp32 accumulate; fp16 output.
// R16: 8 threads/node, each handles 8 halves (one uint4, 16B) per row.
// ---------------------------------------------------------------------------
__global__ void pull64h_kernel(const uint2* __restrict__ hh,
                               const int* __restrict__ rowptr,
                               const int* __restrict__ col,
                               uint2* __restrict__ zh, int n_nodes) {
    int t = blockIdx.x * blockDim.x + threadIdx.x;
    int node = t >> 3, lane = t & 7;
    if (node >= n_nodes) return;
    const uint4* base = (const uint4*)hh;

    float acc[8];
    {
        uint4 u = __ldg(base + (size_t)node * 8 + lane);
        float4 lo = h2f4(make_uint2(u.x, u.y));
        float4 hi = h2f4(make_uint2(u.z, u.w));
        acc[0] = lo.x; acc[1] = lo.y; acc[2] = lo.z; acc[3] = lo.w;
        acc[4] = hi.x; acc[5] = hi.y; acc[6] = hi.z; acc[7] = hi.w;
    }

    int e   = __ldg(rowptr + node);
    int end = __ldg(rowptr + node + 1);
    for (; e + 4 <= end; e += 4) {
        int s0 = __ldg(col + e),     s1 = __ldg(col + e + 1);
        int s2 = __ldg(col + e + 2), s3 = __ldg(col + e + 3);
        uint4 u0 = __ldg(base + (size_t)s0 * 8 + lane);
        uint4 u1 = __ldg(base + (size_t)s1 * 8 + lane);
        uint4 u2 = __ldg(base + (size_t)s2 * 8 + lane);
        uint4 u3 = __ldg(base + (size_t)s3 * 8 + lane);
        acc8(acc, u0); acc8(acc, u1); acc8(acc, u2); acc8(acc, u3);
    }
    for (; e < end; e++) {
        int s = __ldg(col + e);
        acc8(acc, __ldg(base + (size_t)s * 8 + lane));
    }

    uint2 o0 = f4h(acc[0], acc[1], acc[2], acc[3]);
    uint2 o1 = f4h(acc[4], acc[5], acc[6], acc[7]);
    ((uint4*)zh)[(size_t)node * 8 + lane] = make_uint4(o0.x, o0.y, o1.x, o1.y);
}

// ---------------------------------------------------------------------------
// gemmA_hmma: hh = fp16(x @ w1) on tensor cores. (R14-exact: single phase,
// dyn smem As[128][APAD] + Bs[64][BPAD])
// ---------------------------------------------------------------------------
__global__ __launch_bounds__(256) void gemmA_hmma_kernel(
    const float* __restrict__ x, const float* __restrict__ w1,
    uint2* __restrict__ hh, int n_nodes)
{
    extern __shared__ __half dsm[];
    __half* As = dsm;                  // [128][APAD]
    __half* Bs = dsm + 128 * APAD;     // [64][BPAD]
    int tid = threadIdx.x;
    int nbase = blockIdx.x * 128;

    for (int i4 = tid; i4 < 4096; i4 += 256) {
        int row = i4 >> 5, k4 = i4 & 31;
        int gn = nbase + row; if (gn >= n_nodes) gn = n_nodes - 1;
        float4 v = __ldg((const float4*)(x + (size_t)gn * 128) + k4);
        __half2 h0 = __floats2half2_rn(v.x, v.y);
        __half2 h1 = __floats2half2_rn(v.z, v.w);
        unsigned* dst = (unsigned*)&As[row * APAD + k4 * 4];
        dst[0] = *(unsigned*)&h0;
        dst[1] = *(unsigned*)&h1;
    }
    for (int i = tid; i < 128 * 64; i += 256) {
        int k = i >> 6, n = i & 63;
        Bs[n * BPAD + k] = __float2half(__ldg(w1 + i));
    }
    __syncthreads();

    int wid = tid >> 5, lane = tid & 31;
    int r0 = wid * 16 + (lane >> 2);
    int kp = (lane & 3) * 2;

    float c[8][4];
#pragma unroll
    for (int nt = 0; nt < 8; nt++)
#pragma unroll
        for (int j = 0; j < 4; j++) c[nt][j] = 0.f;

#pragma unroll
    for (int kt = 0; kt < 8; kt++) {
        int kb = kt * 16 + kp;
        unsigned a0 = *(unsigned*)&As[r0 * APAD + kb];
        unsigned a1 = *(unsigned*)&As[(r0 + 8) * APAD + kb];
        unsigned a2 = *(unsigned*)&As[r0 * APAD + kb + 8];
        unsigned a3 = *(unsigned*)&As[(r0 + 8) * APAD + kb + 8];
#pragma unroll
        for (int nt = 0; nt < 8; nt++) {
            int n = nt * 8 + (lane >> 2);
            unsigned b0 = *(unsigned*)&Bs[n * BPAD + kb];
            unsigned b1 = *(unsigned*)&Bs[n * BPAD + kb + 8];
            mma16816(c[nt], a0, a1, a2, a3, b0, b1);
        }
    }

    int colp = (lane & 3) * 2;
#pragma unroll
    for (int rr = 0; rr < 2; rr++) {
        int node = nbase + r0 + rr * 8;
        if (node >= n_nodes) continue;
        __half* hrow = (__half*)(hh + (size_t)node * 16);
#pragma unroll
        for (int nt = 0; nt < 8; nt++) {
            __half2 hv = __floats2half2_rn(c[nt][rr * 2 + 0], c[nt][rr * 2 + 1]);
            *(unsigned*)&hrow[nt * 8 + colp] = *(unsigned*)&hv;
        }
    }
}

// ---------------------------------------------------------------------------
// mlpB_hmma (layer-1 tail): h = relu( relu(BN(zh+b1)) @ w2 + b2 ). (R14)
// ---------------------------------------------------------------------------
__global__ __launch_bounds__(256) void mlpB_hmma_kernel(
    const uint2* __restrict__ zh,
    const float* __restrict__ b1,
    const float* __restrict__ gg, const float* __restrict__ bt,
    const float* __restrict__ rm, const float* __restrict__ rv,
    const float* __restrict__ w2, const float* __restrict__ b2,
    uint2*       __restrict__ hh,
    const int*   __restrict__ batch,
    float*       __restrict__ pool, int pool_off, int n_nodes)
{
    __shared__ __half As[128 * MPAD];
    __shared__ __half Bs[64 * MPAD];
    __shared__ float2 scsh[64];
    int tid = threadIdx.x;
    int nbase = blockIdx.x * 128;

    if (tid < 64) {
        float sc = __ldg(gg + tid) * rsqrtf(__ldg(rv + tid) + 1e-5f);
        float sh = (__ldg(b1 + tid) - __ldg(rm + tid)) * sc + __ldg(bt + tid);
        scsh[tid] = make_float2(sc, sh);
    }
    for (int i = tid; i < 64 * 64; i += 256) {
        int k = i >> 6, n = i & 63;
        Bs[n * MPAD + k] = __float2half(__ldg(w2 + i));
    }
    __syncthreads();

    for (int i4 = tid; i4 < 2048; i4 += 256) {
        int row = i4 >> 4, k4 = i4 & 15;
        int gn = nbase + row; if (gn >= n_nodes) gn = n_nodes - 1;
        float4 v = h2f4(__ldg(zh + (size_t)gn * 16 + k4));
        int k = k4 * 4;
        float2 s0 = scsh[k], s1 = scsh[k + 1], s2 = scsh[k + 2], s3 = scsh[k + 3];
        float h0 = fmaxf(fmaf(v.x, s0.x, s0.y), 0.f);
        float h1 = fmaxf(fmaf(v.y, s1.x, s1.y), 0.f);
        float h2v = fmaxf(fmaf(v.z, s2.x, s2.y), 0.f);
        float h3 = fmaxf(fmaf(v.w, s3.x, s3.y), 0.f);
        __half2 p0 = __floats2half2_rn(h0, h1), p1 = __floats2half2_rn(h2v, h3);
        unsigned* dst = (unsigned*)&As[row * MPAD + k];
        dst[0] = *(unsigned*)&p0;
        dst[1] = *(unsigned*)&p1;
    }
    __syncthreads();

    int wid = tid >> 5, lane = tid & 31;
    int r0 = wid * 16 + (lane >> 2);
    int kp = (lane & 3) * 2;

    float c[8][4];
#pragma unroll
    for (int nt = 0; nt < 8; nt++)
#pragma unroll
        for (int j = 0; j < 4; j++) c[nt][j] = 0.f;

#pragma unroll
    for (int kt = 0; kt < 4; kt++) {
        int kb = kt * 16 + kp;
        unsigned a0 = *(unsigned*)&As[r0 * MPAD + kb];
        unsigned a1 = *(unsigned*)&As[(r0 + 8) * MPAD + kb];
        unsigned a2 = *(unsigned*)&As[r0 * MPAD + kb + 8];
        unsigned a3 = *(unsigned*)&As[(r0 + 8) * MPAD + kb + 8];
#pragma unroll
        for (int nt = 0; nt < 8; nt++) {
            int n = nt * 8 + (lane >> 2);
            unsigned b0 = *(unsigned*)&Bs[n * MPAD + kb];
            unsigned b1 = *(unsigned*)&Bs[n * MPAD + kb + 8];
            mma16816(c[nt], a0, a1, a2, a3, b0, b1);
        }
    }

    int colp = (lane & 3) * 2;
#pragma unroll
    for (int rr = 0; rr < 2; rr++) {
        int node = nbase + r0 + rr * 8;
        if (node >= n_nodes) continue;
        __half* hrow = (__half*)(hh + (size_t)node * 16);
        float*  prow = pool + (size_t)__ldg(batch + node) * 192 + pool_off;
#pragma unroll
        for (int nt = 0; nt < 8; nt++) {
            int cA = nt * 8 + colp;
            float v0 = fmaxf(c[nt][rr * 2 + 0] + __ldg(b2 + cA), 0.f);
            float v1 = fmaxf(c[nt][rr * 2 + 1] + __ldg(b2 + cA + 1), 0.f);
            __half2 hv = __floats2half2_rn(v0, v1);
            *(unsigned*)&hrow[cA] = *(unsigned*)&hv;
            asm volatile("red.global.add.v2.f32 [%0], {%1,%2};"
                         :: "l"(prow + cA), "f"(v0), "f"(v1) : "memory");
        }
    }
}

// ---------------------------------------------------------------------------
// mlp64_hmma (layers 2/3). (R14)
// ---------------------------------------------------------------------------
__global__ __launch_bounds__(256) void mlp64_hmma_kernel(
    const uint2* __restrict__ zh,
    const float* __restrict__ w1, const float* __restrict__ b1,
    const float* __restrict__ gg, const float* __restrict__ bt,
    const float* __restrict__ rm, const float* __restrict__ rv,
    const float* __restrict__ w2, const float* __restrict__ b2,
    uint2*       __restrict__ hh,
    const int*   __restrict__ batch,
    float*       __restrict__ pool, int pool_off, int n_nodes)
{
    __shared__ __half As[128 * MPAD];
    __shared__ __half Bs[64 * MPAD];
    __shared__ float2 scsh[64];
    int tid = threadIdx.x;
    int nbase = blockIdx.x * 128;

    if (tid < 64) {
        float sc = __ldg(gg + tid) * rsqrtf(__ldg(rv + tid) + 1e-5f);
        float sh = (__ldg(b1 + tid) - __ldg(rm + tid)) * sc + __ldg(bt + tid);
        scsh[tid] = make_float2(sc, sh);
    }
    for (int i = tid; i < 64 * 64; i += 256) {
        int k = i >> 6, n = i & 63;
        Bs[n * MPAD + k] = __float2half(__ldg(w1 + i));
    }
    for (int i = tid; i < 1024; i += 256) {
        int row = i >> 3, q4 = i & 7;
        int gn = nbase + row; if (gn >= n_nodes) gn = n_nodes - 1;
        uint4 v = __ldg((const uint4*)(zh + (size_t)gn * 16) + q4);
        *(uint4*)&As[row * MPAD + q4 * 8] = v;
    }
    __syncthreads();

    int wid = tid >> 5, lane = tid & 31;
    int r0 = wid * 16 + (lane >> 2);
    int kp = (lane & 3) * 2;
    int colp = (lane & 3) * 2;

    float c[8][4];
#pragma unroll
    for (int nt = 0; nt < 8; nt++)
#pragma unroll
        for (int j = 0; j < 4; j++) c[nt][j] = 0.f;

#pragma unroll
    for (int kt = 0; kt < 4; kt++) {
        int kb = kt * 16 + kp;
        unsigned a0 = *(unsigned*)&As[r0 * MPAD + kb];
        unsigned a1 = *(unsigned*)&As[(r0 + 8) * MPAD + kb];
        unsigned a2 = *(unsigned*)&As[r0 * MPAD + kb + 8];
        unsigned a3 = *(unsigned*)&As[(r0 + 8) * MPAD + kb + 8];
#pragma unroll
        for (int nt = 0; nt < 8; nt++) {
            int n = nt * 8 + (lane >> 2);
            unsigned b0 = *(unsigned*)&Bs[n * MPAD + kb];
            unsigned b1 = *(unsigned*)&Bs[n * MPAD + kb + 8];
            mma16816(c[nt], a0, a1, a2, a3, b0, b1);
        }
    }

#pragma unroll
    for (int nt = 0; nt < 8; nt++) {
        int cA = nt * 8 + colp, cB = cA + 1;
        float2 sA = scsh[cA], sB = scsh[cB];
        float h00 = fmaxf(fmaf(c[nt][0], sA.x, sA.y), 0.f);
        float h01 = fmaxf(fmaf(c[nt][1], sB.x, sB.y), 0.f);
        float h10 = fmaxf(fmaf(c[nt][2], sA.x, sA.y), 0.f);
        float h11 = fmaxf(fmaf(c[nt][3], sB.x, sB.y), 0.f);
        __half2 p0 = __floats2half2_rn(h00, h01);
        __half2 p1 = __floats2half2_rn(h10, h11);
        *(unsigned*)&As[r0 * MPAD + cA]       = *(unsigned*)&p0;
        *(unsigned*)&As[(r0 + 8) * MPAD + cA] = *(unsigned*)&p1;
    }
    __syncthreads();

    for (int i = tid; i < 64 * 64; i += 256) {
        int k = i >> 6, n = i & 63;
        Bs[n * MPAD + k] = __float2half(__ldg(w2 + i));
    }
    __syncthreads();

#pragma unroll
    for (int nt = 0; nt < 8; nt++)
#pragma unroll
        for (int j = 0; j < 4; j++) c[nt][j] = 0.f;

#pragma unroll
    for (int kt = 0; kt < 4; kt++) {
        int kb = kt * 16 + kp;
        unsigned a0 = *(unsigned*)&As[r0 * MPAD + kb];
        unsigned a1 = *(unsigned*)&As[(r0 + 8) * MPAD + kb];
        unsigned a2 = *(unsigned*)&As[r0 * MPAD + kb + 8];
        unsigned a3 = *(unsigned*)&As[(r0 + 8) * MPAD + kb + 8];
#pragma unroll
        for (int nt = 0; nt < 8; nt++) {
            int n = nt * 8 + (lane >> 2);
            unsigned b0 = *(unsigned*)&Bs[n * MPAD + kb];
            unsigned b1 = *(unsigned*)&Bs[n * MPAD + kb + 8];
            mma16816(c[nt], a0, a1, a2, a3, b0, b1);
        }
    }

#pragma unroll
    for (int rr = 0; rr < 2; rr++) {
        int node = nbase + r0 + rr * 8;
        if (node >= n_nodes) continue;
        __half* hrow = (__half*)(hh + (size_t)node * 16);
        float*  prow = pool + (size_t)__ldg(batch + node) * 192 + pool_off;
#pragma unroll
        for (int nt = 0; nt < 8; nt++) {
            int cA = nt * 8 + colp;
            float v0 = fmaxf(c[nt][rr * 2 + 0] + __ldg(b2 + cA), 0.f);
            float v1 = fmaxf(c[nt][rr * 2 + 1] + __ldg(b2 + cA + 1), 0.f);
            __half2 hv = __floats2half2_rn(v0, v1);
            *(unsigned*)&hrow[cA] = *(unsigned*)&hv;
            asm volatile("red.global.add.v2.f32 [%0], {%1,%2};"
                         :: "l"(prow + cA), "f"(v0), "f"(v1) : "memory");
        }
    }
}

// ---------------------------------------------------------------------------
__global__ void final_kernel(const float* __restrict__ pool,
                             const float* __restrict__ lw1, const float* __restrict__ lb1,
                             const float* __restrict__ lw2, const float* __restrict__ lb2,
                             float* __restrict__ out)
{
    __shared__ float prow[192];
    __shared__ float hid[64];
    __shared__ float zz[2];
    int g = blockIdx.x, j = threadIdx.x;
    for (int k = j; k < 192; k += 64) prow[k] = pool[g * 192 + k];
    __syncthreads();
    float a = __ldg(lb1 + j);
    for (int k = 0; k < 192; k++) a = fmaf(prow[k], __ldg(lw1 + k * 64 + j), a);
    hid[j] = fmaxf(a, 0.f);
    __syncthreads();
    if (j < 2) {
        float zv = __ldg(lb2 + j);
#pragma unroll 8
        for (int k = 0; k < 64; k++) zv = fmaf(hid[k], __ldg(lw2 + k * 2 + j), zv);
        zz[j] = zv;
    }
    __syncthreads();
    if (j == 0) {
        float m   = fmaxf(zz[0], zz[1]);
        float lse = m + logf(expf(zz[0] - m) + expf(zz[1] - m));
        out[g * 2 + 0] = zz[0] - lse;
        out[g * 2 + 1] = zz[1] - lse;
    }
}

// ---------------------------------------------------------------------------
extern "C" void kernel_launch(void* const* d_in, const int* in_sizes, int n_in,
                              void* d_out, int out_size)
{
    const float* x     = (const float*)d_in[0];
    const int*   ei    = (const int*)  d_in[1];
    const int*   batch = (const int*)  d_in[2];

    int wi = (in_sizes[3] < 64) ? 4 : 3;
    const float* W[28];
    for (int i = 0; i < 28 && wi + i < n_in; i++) W[i] = (const float*)d_in[wi + i];

    int n_nodes = in_sizes[0] / 128;
    int n_edges = in_sizes[1] / 2;

    float *pool;
    uint2 *hh, *zh;
    int *deg, *row, *cur, *col, *bsum;
    cudaGetSymbolAddress((void**)&zh,   g_zh);
    cudaGetSymbolAddress((void**)&hh,   g_hh);
    cudaGetSymbolAddress((void**)&pool, g_pool);
    cudaGetSymbolAddress((void**)&deg,  g_deg);
    cudaGetSymbolAddress((void**)&row,  g_row);
    cudaGetSymbolAddress((void**)&cur,  g_cur);
    cudaGetSymbolAddress((void**)&col,  g_col);
    cudaGetSymbolAddress((void**)&bsum, g_bsum);

    float* out = (float*)d_out;

    const int SM_GA = (128 * APAD + 64 * BPAD) * 2;   // ~52KB dyn smem (gemmA)
    cudaFuncSetAttribute(gemmA_hmma_kernel,
                         cudaFuncAttributeMaxDynamicSharedMemorySize, SM_GA);

    int mlpBlocks  = (n_nodes + 127) / 128;
    int pullBlocks = (n_nodes * 8 + 255) / 256;       // 8 threads/node now
    int scanBlocks = (n_nodes + SCAN_B - 1) / SCAN_B;
    int zeroN      = n_nodes + 1;

    // ---- CSR build; gemmA_hmma is OUR launch #4 (profiled) ----
    zero_both_kernel<<<(zeroN + 255) / 256, 256>>>(deg, zeroN, pool, NGRAPH * 192); // 1
    hist_kernel<<<(n_edges + 255) / 256, 256>>>(ei, deg, n_edges);                  // 2
    bsum_kernel<<<scanBlocks, SCAN_B>>>(deg, bsum, n_nodes);                        // 3
    gemmA_hmma_kernel<<<mlpBlocks, 256, SM_GA>>>(x, W[0], hh, n_nodes);             // 4
    scatter_scan_kernel<<<scanBlocks, SCAN_B>>>(deg, bsum, row, cur, n_nodes);      // 5
    fill_kernel<<<(n_edges + 255) / 256, 256>>>(ei, cur, col, n_edges);             // 6

    // ---- layer 1 ----
    pull64h_kernel<<<pullBlocks, 256>>>(hh, row, col, zh, n_nodes);                 // 7
    mlpB_hmma_kernel<<<mlpBlocks, 256>>>(zh, W[1], W[2], W[3], W[4], W[5], W[6], W[7],
                                         hh, batch, pool, 0, n_nodes);              // 8

    // ---- layer 2 ----
    pull64h_kernel<<<pullBlocks, 256>>>(hh, row, col, zh, n_nodes);                 // 9
    mlp64_hmma_kernel<<<mlpBlocks, 256>>>(zh, W[8], W[9], W[10], W[11], W[12], W[13], W[14], W[15],
                                          hh, batch, pool, 64, n_nodes);            // 10

    // ---- layer 3 ----
    pull64h_kernel<<<pullBlocks, 256>>>(hh, row, col, zh, n_nodes);                 // 11
    mlp64_hmma_kernel<<<mlpBlocks, 256>>>(zh, W[16], W[17], W[18], W[19], W[20], W[21], W[22], W[23],
                                          hh, batch, pool, 128, n_nodes);           // 12

    final_kernel<<<NGRAPH, 64>>>(pool, W[24], W[25], W[26], W[27], out);            // 13
}